// round 4
// baseline (speedup 1.0000x reference)
#include <cuda_runtime.h>
#include <math.h>

// Shapes (fixed by the problem)
#define BB  2
#define NN  512
#define HID 128
#define DD  64    // Chebyshev orders (degree DD-1)

// node_eval tiling
#define NODES 4                    // Chebyshev nodes per block
#define KSPL  4                    // k-dimension split
#define NE_THREADS (HID * KSPL)    // 512

// Scratch (static device globals; no allocation)
__device__ float g_G[DD * HID];   // network(+Wo) evaluated at Chebyshev nodes
__device__ float g_C[DD * HID];   // Chebyshev coefficients of G

// ---------------------------------------------------------------------------
// Kernel 1: evaluate the exact fp32 network at DD Chebyshev nodes, fold Wo.
// 16 blocks x 512 threads; thread (q,c): q = k-quarter, c = output column.
// 4 nodes/block -> 4 independent FMA chains per thread; chain length 32.
// Computes dmax inline (deterministic, identical in every block).
// ---------------------------------------------------------------------------
__global__ __launch_bounds__(NE_THREADS) void node_eval_kernel(
    const float* __restrict__ x,
    const float* __restrict__ W10, const float* __restrict__ b10,
    const float* __restrict__ W20, const float* __restrict__ b20,
    const float* __restrict__ W11, const float* __restrict__ b11,
    const float* __restrict__ W21, const float* __restrict__ b21,
    const float* __restrict__ W12, const float* __restrict__ b12,
    const float* __restrict__ W22, const float* __restrict__ b22,
    const float* __restrict__ Wo)
{
    __shared__ float red[NE_THREADS];
    __shared__ float buf[NODES][HID];         // current activations
    __shared__ float part[KSPL][NODES][HID];  // per-quarter partial sums

    // dmax = 2*max||x|| (triangle inequality bound), deterministic
    float mx = 0.0f;
    for (int t = threadIdx.x; t < BB * NN; t += NE_THREADS) {
        float a = x[2 * t], b = x[2 * t + 1];
        mx = fmaxf(mx, fmaf(a, a, b * b));
    }
    red[threadIdx.x] = mx;
    __syncthreads();
    #pragma unroll
    for (int s = NE_THREADS / 2; s > 0; s >>= 1) {
        if (threadIdx.x < s) red[threadIdx.x] = fmaxf(red[threadIdx.x], red[threadIdx.x + s]);
        __syncthreads();
    }
    const float dmax = 2.0f * sqrtf(red[0]) * 1.000001f + 1e-6f;

    const int c = threadIdx.x & (HID - 1);
    const int q = threadIdx.x >> 7;          // 0..3  (NODES == KSPL == 4)

    // layer 0 (scalar input): thread-set q computes node q of this block
    {
        int mnode = blockIdx.x * NODES + q;
        float d = 0.5f * (cospif((mnode + 0.5f) * (1.0f / DD)) + 1.0f) * dmax;
        float a = fmaf(d, W10[c], b10[c]);
        buf[q][c] = a / (1.0f + expf(-a));
    }
    __syncthreads();

    const float* Ws[6] = {W20, W11, W21, W12, W22, Wo};
    const float* bs[6] = {b20, b11, b21, b12, b22, (const float*)0};
    #pragma unroll
    for (int l = 0; l < 6; l++) {
        const float* __restrict__ W = Ws[l];
        float h0 = 0.0f, h1 = 0.0f, h2 = 0.0f, h3 = 0.0f;
        const int k0 = q * (HID / KSPL);
        #pragma unroll
        for (int kk = 0; kk < HID / KSPL; kk++) {
            const int k = k0 + kk;
            const float w = W[k * HID + c];
            h0 = fmaf(buf[0][k], w, h0);
            h1 = fmaf(buf[1][k], w, h1);
            h2 = fmaf(buf[2][k], w, h2);
            h3 = fmaf(buf[3][k], w, h3);
        }
        part[q][0][c] = h0;
        part[q][1][c] = h1;
        part[q][2][c] = h2;
        part[q][3][c] = h3;
        __syncthreads();
        // thread-set q finalizes node q
        float v = (bs[l] ? bs[l][c] : 0.0f) +
                  ((part[0][q][c] + part[1][q][c]) + (part[2][q][c] + part[3][q][c]));
        if (l == 1 || l == 3) v = v / (1.0f + expf(-v));   // silu after W1_1, W1_2
        if (l < 5) buf[q][c] = v;                          // no race: buf reads done pre-sync
        else g_G[(blockIdx.x * NODES + q) * HID + c] = v;
        __syncthreads();
    }
}

// ---------------------------------------------------------------------------
// Kernel 2: DCT-II -> Chebyshev coefficients.
// Angle = pi*k(2m+1)/(2*DD) = pi*num/128, num integer exact in fp32,
// reduced mod 256 (cospi period 2) -> cospif is bit-accurate.
// ---------------------------------------------------------------------------
__global__ __launch_bounds__(HID) void dct_kernel() {
    const int k = blockIdx.x, c = threadIdx.x;
    float acc = 0.0f;
    #pragma unroll 8
    for (int m = 0; m < DD; m++) {
        int num = (k * (2 * m + 1)) & 255;
        float t = cospif((float)num * (1.0f / 128.0f));
        acc = fmaf(t, g_G[m * HID + c], acc);
    }
    float wgt = (k == 0) ? (1.0f / DD) : (2.0f / DD);
    g_C[k * HID + c] = acc * wgt;
}

// ---------------------------------------------------------------------------
// Kernel 3 (hot): per (b,i), s[k] = sum_j T_k(z_ij); out = (1/N) s@C + bo.
// 1 warp per row, 4 rows (128 thr) per block, 256 blocks.
// 4 independent recurrence chains per lane hide FMA lat-4.
// Cross-lane reduction = reduce-scatter butterfly (62 shfl instead of ~635).
// ---------------------------------------------------------------------------
__global__ __launch_bounds__(128, 4) void cheb_main_kernel(
    const float* __restrict__ x, const float* __restrict__ bo,
    float* __restrict__ out)
{
    __shared__ float red[128];
    __shared__ float sx[NN * 2];
    __shared__ float sred[4][DD];          // reduced s per warp

    // deterministic dmax (identical to node_eval's value)
    float mx = 0.0f;
    for (int t = threadIdx.x; t < BB * NN; t += 128) {
        float a = x[2 * t], b = x[2 * t + 1];
        mx = fmaxf(mx, fmaf(a, a, b * b));
    }
    red[threadIdx.x] = mx;
    __syncthreads();
    #pragma unroll
    for (int s = 64; s > 0; s >>= 1) {
        if (threadIdx.x < s) red[threadIdx.x] = fmaxf(red[threadIdx.x], red[threadIdx.x + s]);
        __syncthreads();
    }
    const float inv_hd = 2.0f / (2.0f * sqrtf(red[0]) * 1.000001f + 1e-6f);
    __syncthreads();

    const int b = blockIdx.x >> 7;         // 128 blocks per batch
    for (int t = threadIdx.x; t < NN * 2; t += 128) sx[t] = x[b * NN * 2 + t];
    __syncthreads();

    const int w    = threadIdx.x >> 5;
    const int lane = threadIdx.x & 31;
    const int i    = ((blockIdx.x & 127) << 2) + w;   // row within batch
    const float xi0 = sx[2 * i], xi1 = sx[2 * i + 1];

    float s[DD];
    #pragma unroll
    for (int k = 0; k < DD; k++) s[k] = 0.0f;

    #pragma unroll 1
    for (int j0 = 0; j0 < NN; j0 += 128) {
        const int ja = j0 + lane, jb = ja + 32, jc = ja + 64, jd = ja + 96;
        float dxa = xi0 - sx[2 * ja], dya = xi1 - sx[2 * ja + 1];
        float dxb = xi0 - sx[2 * jb], dyb = xi1 - sx[2 * jb + 1];
        float dxc = xi0 - sx[2 * jc], dyc = xi1 - sx[2 * jc + 1];
        float dxd = xi0 - sx[2 * jd], dyd = xi1 - sx[2 * jd + 1];
        float za = fmaf(sqrtf(fmaf(dxa, dxa, dya * dya)), inv_hd, -1.0f);
        float zb = fmaf(sqrtf(fmaf(dxb, dxb, dyb * dyb)), inv_hd, -1.0f);
        float zc = fmaf(sqrtf(fmaf(dxc, dxc, dyc * dyc)), inv_hd, -1.0f);
        float zd = fmaf(sqrtf(fmaf(dxd, dxd, dyd * dyd)), inv_hd, -1.0f);
        za = fminf(fmaxf(za, -1.0f), 1.0f);
        zb = fminf(fmaxf(zb, -1.0f), 1.0f);
        zc = fminf(fmaxf(zc, -1.0f), 1.0f);
        zd = fminf(fmaxf(zd, -1.0f), 1.0f);

        s[1] += (za + zb) + (zc + zd);
        float t0a = 1.0f, t1a = za, z2a = za + za;
        float t0b = 1.0f, t1b = zb, z2b = zb + zb;
        float t0c = 1.0f, t1c = zc, z2c = zc + zc;
        float t0d = 1.0f, t1d = zd, z2d = zd + zd;
        #pragma unroll
        for (int k = 2; k < DD; k++) {
            float ta = fmaf(z2a, t1a, -t0a); t0a = t1a; t1a = ta;
            float tb = fmaf(z2b, t1b, -t0b); t0b = t1b; t1b = tb;
            float tc = fmaf(z2c, t1c, -t0c); t0c = t1c; t1c = tc;
            float td = fmaf(z2d, t1d, -t0d); t0d = t1d; t1d = td;
            s[k] += (ta + tb) + (tc + td);
        }
    }
    // T_0 == 1: each lane processed NN/32 = 16 source nodes
    s[0] = (float)(NN / 32);

    // reduce-scatter butterfly: after 5 stages lane holds k = 2*lane + {0,1}
    int len = DD / 2;
    #pragma unroll
    for (int off = 16; off > 0; off >>= 1) {
        const bool hi = (lane & off) != 0;
        #pragma unroll
        for (int k = 0; k < 32; k++) {     // bounded by first-stage len
            if (k >= len) break;
            float send = hi ? s[k] : s[k + len];
            float recv = __shfl_xor_sync(0xffffffffu, send, off);
            s[k] = (hi ? s[k + len] : s[k]) + recv;
        }
        len >>= 1;
    }
    sred[w][2 * lane]     = s[0];
    sred[w][2 * lane + 1] = s[1];
    __syncwarp();

    // out_c = (1/N) * sum_k s[k]*C[k][c] + bo[c]; each lane owns 4 columns
    const float sc = 1.0f / (float)NN;
    const int c0 = lane * 4;
    float4 acc = make_float4(bo[c0], bo[c0 + 1], bo[c0 + 2], bo[c0 + 3]);
    #pragma unroll 8
    for (int k = 0; k < DD; k++) {
        float4 wv = *reinterpret_cast<const float4*>(&g_C[k * HID + c0]);
        float sk = sred[w][k] * sc;
        acc.x = fmaf(sk, wv.x, acc.x);
        acc.y = fmaf(sk, wv.y, acc.y);
        acc.z = fmaf(sk, wv.z, acc.z);
        acc.w = fmaf(sk, wv.w, acc.w);
    }
    const int gi = b * NN + i;
    reinterpret_cast<float4*>(out)[gi * (HID / 4) + lane] = acc;
}

// ---------------------------------------------------------------------------
// Launch: 3 graph-capturable kernels, stream-ordered dependencies.
// Input order: x, W1_0,b1_0,W2_0,b2_0, W1_1,b1_1,W2_1,b2_1, W1_2,b1_2,W2_2,b2_2, Wo,bo
// ---------------------------------------------------------------------------
extern "C" void kernel_launch(void* const* d_in, const int* in_sizes, int n_in,
                              void* d_out, int out_size)
{
    const float* x   = (const float*)d_in[0];
    const float* W10 = (const float*)d_in[1];
    const float* b10 = (const float*)d_in[2];
    const float* W20 = (const float*)d_in[3];
    const float* b20 = (const float*)d_in[4];
    const float* W11 = (const float*)d_in[5];
    const float* b11 = (const float*)d_in[6];
    const float* W21 = (const float*)d_in[7];
    const float* b21 = (const float*)d_in[8];
    const float* W12 = (const float*)d_in[9];
    const float* b12 = (const float*)d_in[10];
    const float* W22 = (const float*)d_in[11];
    const float* b22 = (const float*)d_in[12];
    const float* Wo  = (const float*)d_in[13];
    const float* bo  = (const float*)d_in[14];
    float* out = (float*)d_out;

    node_eval_kernel<<<DD / NODES, NE_THREADS>>>(x, W10, b10, W20, b20, W11, b11,
                                                 W21, b21, W12, b12, W22, b22, Wo);
    dct_kernel<<<DD, HID>>>();
    cheb_main_kernel<<<(BB * NN) / 4, 128>>>(x, bo, out);
}

// round 5
// speedup vs baseline: 1.4368x; 1.4368x over previous
#include <cuda_runtime.h>
#include <math.h>

// Shapes (fixed by the problem)
#define BB  2
#define NN  512
#define HID 128
#define DD  64    // Chebyshev orders (degree DD-1)

// node_eval tiling
#define NODES 4                    // Chebyshev nodes per block
#define KSPL  4                    // k-dimension split
#define NE_THREADS (HID * KSPL)    // 512

// Scratch (static device globals; no allocation)
__device__ float g_inv_hd;        // 2 / dmax, published by node_eval block 0
__device__ float g_G[DD * HID];   // network(+Wo) evaluated at Chebyshev nodes
__device__ float g_C[DD * HID];   // Chebyshev coefficients of G

// ---------------------------------------------------------------------------
// Kernel 1: evaluate the exact fp32 network at DD Chebyshev nodes, fold Wo.
// 16 blocks x 512 threads; thread (q,c): q = k-quarter, c = output column.
// Computes dmax inline (deterministic, identical in every block); block 0
// publishes g_inv_hd for the main kernel.
// ---------------------------------------------------------------------------
__global__ __launch_bounds__(NE_THREADS) void node_eval_kernel(
    const float* __restrict__ x,
    const float* __restrict__ W10, const float* __restrict__ b10,
    const float* __restrict__ W20, const float* __restrict__ b20,
    const float* __restrict__ W11, const float* __restrict__ b11,
    const float* __restrict__ W21, const float* __restrict__ b21,
    const float* __restrict__ W12, const float* __restrict__ b12,
    const float* __restrict__ W22, const float* __restrict__ b22,
    const float* __restrict__ Wo)
{
    __shared__ float red[NE_THREADS];
    __shared__ float buf[NODES][HID];         // current activations
    __shared__ float part[KSPL][NODES][HID];  // per-quarter partial sums

    // dmax = 2*max||x|| (triangle inequality bound), deterministic
    float mx = 0.0f;
    for (int t = threadIdx.x; t < BB * NN; t += NE_THREADS) {
        float a = x[2 * t], b = x[2 * t + 1];
        mx = fmaxf(mx, fmaf(a, a, b * b));
    }
    red[threadIdx.x] = mx;
    __syncthreads();
    #pragma unroll
    for (int s = NE_THREADS / 2; s > 0; s >>= 1) {
        if (threadIdx.x < s) red[threadIdx.x] = fmaxf(red[threadIdx.x], red[threadIdx.x + s]);
        __syncthreads();
    }
    const float dmax = 2.0f * sqrtf(red[0]) * 1.000001f + 1e-6f;
    if (blockIdx.x == 0 && threadIdx.x == 0) g_inv_hd = 2.0f / dmax;

    const int c = threadIdx.x & (HID - 1);
    const int q = threadIdx.x >> 7;          // 0..3  (NODES == KSPL == 4)

    // layer 0 (scalar input): thread-set q computes node q of this block
    {
        int mnode = blockIdx.x * NODES + q;
        float d = 0.5f * (cospif((mnode + 0.5f) * (1.0f / DD)) + 1.0f) * dmax;
        float a = fmaf(d, W10[c], b10[c]);
        buf[q][c] = a / (1.0f + expf(-a));
    }
    __syncthreads();

    const float* Ws[6] = {W20, W11, W21, W12, W22, Wo};
    const float* bs[6] = {b20, b11, b21, b12, b22, (const float*)0};
    #pragma unroll
    for (int l = 0; l < 6; l++) {
        const float* __restrict__ W = Ws[l];
        float h0 = 0.0f, h1 = 0.0f, h2 = 0.0f, h3 = 0.0f;
        const int k0 = q * (HID / KSPL);
        #pragma unroll
        for (int kk = 0; kk < HID / KSPL; kk++) {
            const int k = k0 + kk;
            const float w = W[k * HID + c];
            h0 = fmaf(buf[0][k], w, h0);
            h1 = fmaf(buf[1][k], w, h1);
            h2 = fmaf(buf[2][k], w, h2);
            h3 = fmaf(buf[3][k], w, h3);
        }
        part[q][0][c] = h0;
        part[q][1][c] = h1;
        part[q][2][c] = h2;
        part[q][3][c] = h3;
        __syncthreads();
        // thread-set q finalizes node q
        float v = (bs[l] ? bs[l][c] : 0.0f) +
                  ((part[0][q][c] + part[1][q][c]) + (part[2][q][c] + part[3][q][c]));
        if (l == 1 || l == 3) v = v / (1.0f + expf(-v));   // silu after W1_1, W1_2
        if (l < 5) buf[q][c] = v;                          // no race: buf reads done pre-sync
        else g_G[(blockIdx.x * NODES + q) * HID + c] = v;
        __syncthreads();
    }
}

// ---------------------------------------------------------------------------
// Kernel 2: DCT-II -> Chebyshev coefficients.
// Angle = pi*k(2m+1)/(2*DD) = pi*num/128, num integer exact in fp32,
// reduced mod 256 (cospi period 2) -> cospif is bit-accurate.
// ---------------------------------------------------------------------------
__global__ __launch_bounds__(HID) void dct_kernel() {
    const int k = blockIdx.x, c = threadIdx.x;
    float acc = 0.0f;
    #pragma unroll 8
    for (int m = 0; m < DD; m++) {
        int num = (k * (2 * m + 1)) & 255;
        float t = cospif((float)num * (1.0f / 128.0f));
        acc = fmaf(t, g_G[m * HID + c], acc);
    }
    float wgt = (k == 0) ? (1.0f / DD) : (2.0f / DD);
    g_C[k * HID + c] = acc * wgt;
}

// ---------------------------------------------------------------------------
// Kernel 3 (hot): per (b,i), s[k] = sum_j T_k(z_ij); out = (1/N) s@C + bo.
// 512 blocks x 128 thr: block = 2 rows, each row = 2 warps (j-split 256 each).
// Per lane: 4 independent recurrence chains (hide FMA lat-4), 2 outer iters.
// Cross-lane: reduce-scatter butterfly (lane ends with k = 2L, 2L+1).
// Cross-warp: smem add. Epilogue: the row's 2 warps split columns (64 each).
// ---------------------------------------------------------------------------
__global__ __launch_bounds__(128, 4) void cheb_main_kernel(
    const float* __restrict__ x, const float* __restrict__ bo,
    float* __restrict__ out)
{
    __shared__ float sx[NN * 2];
    __shared__ float sred[4][DD];          // per-warp reduced s

    const float inv_hd = g_inv_hd;         // published by node_eval

    const int b = blockIdx.x >> 8;         // 256 blocks per batch
    for (int t = threadIdx.x; t < NN * 2; t += 128) sx[t] = x[b * NN * 2 + t];
    __syncthreads();

    const int w    = threadIdx.x >> 5;     // warp 0..3
    const int lane = threadIdx.x & 31;
    const int r    = w >> 1;               // row-in-block 0..1
    const int h    = w & 1;                // j-half 0..1
    const int i    = ((blockIdx.x & 255) << 1) + r;   // row within batch
    const float xi0 = sx[2 * i], xi1 = sx[2 * i + 1];

    float s[DD];
    #pragma unroll
    for (int k = 0; k < DD; k++) s[k] = 0.0f;

    #pragma unroll 1
    for (int jj = 0; jj < 2; jj++) {
        const int j0 = h * 256 + jj * 128;
        const int ja = j0 + lane, jb = ja + 32, jc = ja + 64, jd = ja + 96;
        float dxa = xi0 - sx[2 * ja], dya = xi1 - sx[2 * ja + 1];
        float dxb = xi0 - sx[2 * jb], dyb = xi1 - sx[2 * jb + 1];
        float dxc = xi0 - sx[2 * jc], dyc = xi1 - sx[2 * jc + 1];
        float dxd = xi0 - sx[2 * jd], dyd = xi1 - sx[2 * jd + 1];
        float za = fmaf(sqrtf(fmaf(dxa, dxa, dya * dya)), inv_hd, -1.0f);
        float zb = fmaf(sqrtf(fmaf(dxb, dxb, dyb * dyb)), inv_hd, -1.0f);
        float zc = fmaf(sqrtf(fmaf(dxc, dxc, dyc * dyc)), inv_hd, -1.0f);
        float zd = fmaf(sqrtf(fmaf(dxd, dxd, dyd * dyd)), inv_hd, -1.0f);
        za = fminf(fmaxf(za, -1.0f), 1.0f);
        zb = fminf(fmaxf(zb, -1.0f), 1.0f);
        zc = fminf(fmaxf(zc, -1.0f), 1.0f);
        zd = fminf(fmaxf(zd, -1.0f), 1.0f);

        s[1] += (za + zb) + (zc + zd);
        float t0a = 1.0f, t1a = za, z2a = za + za;
        float t0b = 1.0f, t1b = zb, z2b = zb + zb;
        float t0c = 1.0f, t1c = zc, z2c = zc + zc;
        float t0d = 1.0f, t1d = zd, z2d = zd + zd;
        #pragma unroll
        for (int k = 2; k < DD; k++) {
            float ta = fmaf(z2a, t1a, -t0a); t0a = t1a; t1a = ta;
            float tb = fmaf(z2b, t1b, -t0b); t0b = t1b; t1b = tb;
            float tc = fmaf(z2c, t1c, -t0c); t0c = t1c; t1c = tc;
            float td = fmaf(z2d, t1d, -t0d); t0d = t1d; t1d = td;
            s[k] += (ta + tb) + (tc + td);
        }
    }
    // T_0 == 1: each lane processed 256/32 = 8 source nodes
    s[0] = 8.0f;

    // reduce-scatter butterfly: after 5 stages lane holds k = 2*lane + {0,1}
    int len = DD / 2;
    #pragma unroll
    for (int off = 16; off > 0; off >>= 1) {
        const bool hi = (lane & off) != 0;
        #pragma unroll
        for (int k = 0; k < 32; k++) {     // bounded by first-stage len
            if (k >= len) break;
            float send = hi ? s[k] : s[k + len];
            float recv = __shfl_xor_sync(0xffffffffu, send, off);
            s[k] = (hi ? s[k + len] : s[k]) + recv;
        }
        len >>= 1;
    }
    sred[w][2 * lane]     = s[0];
    sred[w][2 * lane + 1] = s[1];
    __syncthreads();

    // combine the row's two j-halves and contract with C.
    // Each warp handles 64 of the row's 128 output columns (float2 per lane).
    const float sc = 1.0f / (float)NN;
    const int c0 = h * 64 + lane * 2;
    float accx = bo[c0], accy = bo[c0 + 1];
    #pragma unroll 8
    for (int k = 0; k < DD; k++) {
        float sk = (sred[2 * r][k] + sred[2 * r + 1][k]) * sc;
        float2 wv = *reinterpret_cast<const float2*>(&g_C[k * HID + c0]);
        accx = fmaf(sk, wv.x, accx);
        accy = fmaf(sk, wv.y, accy);
    }
    const int gi = b * NN + i;
    *reinterpret_cast<float2*>(&out[gi * HID + c0]) = make_float2(accx, accy);
}

// ---------------------------------------------------------------------------
// Launch: 3 graph-capturable kernels, stream-ordered dependencies.
// Input order: x, W1_0,b1_0,W2_0,b2_0, W1_1,b1_1,W2_1,b2_1, W1_2,b1_2,W2_2,b2_2, Wo,bo
// ---------------------------------------------------------------------------
extern "C" void kernel_launch(void* const* d_in, const int* in_sizes, int n_in,
                              void* d_out, int out_size)
{
    const float* x   = (const float*)d_in[0];
    const float* W10 = (const float*)d_in[1];
    const float* b10 = (const float*)d_in[2];
    const float* W20 = (const float*)d_in[3];
    const float* b20 = (const float*)d_in[4];
    const float* W11 = (const float*)d_in[5];
    const float* b11 = (const float*)d_in[6];
    const float* W21 = (const float*)d_in[7];
    const float* b21 = (const float*)d_in[8];
    const float* W12 = (const float*)d_in[9];
    const float* b12 = (const float*)d_in[10];
    const float* W22 = (const float*)d_in[11];
    const float* b22 = (const float*)d_in[12];
    const float* Wo  = (const float*)d_in[13];
    const float* bo  = (const float*)d_in[14];
    float* out = (float*)d_out;

    node_eval_kernel<<<DD / NODES, NE_THREADS>>>(x, W10, b10, W20, b20, W11, b11,
                                                 W21, b21, W12, b12, W22, b22, Wo);
    dct_kernel<<<DD, HID>>>();
    cheb_main_kernel<<<(BB * NN) / 2, 128>>>(x, bo, out);
}

// round 6
// speedup vs baseline: 1.7827x; 1.2407x over previous
#include <cuda_runtime.h>
#include <math.h>

// Shapes (fixed by the problem)
#define BB  2
#define NN  512
#define HID 128
#define DD  48    // Chebyshev orders; measured rho>=1.29 -> truncation <= 4.6e-6
#define SPAD 64   // padded order count for power-of-2 butterfly

// fused prologue tiling
#define NODES 4                    // Chebyshev nodes per block
#define KSPL  4                    // k-dimension split
#define NE_BLOCKS (DD / NODES)     // 12
#define NE_THREADS (HID * KSPL)    // 512

// Scratch (static device globals; no allocation)
__device__ float g_inv_hd;        // 2 / dmax
__device__ float g_G[DD * HID];   // network(+Wo) at Chebyshev nodes
__device__ float g_C[DD * HID];   // Chebyshev coefficients
__device__ unsigned g_arrive;     // grid barrier counter (0 at start AND end of every launch)

// ---------------------------------------------------------------------------
// Fused prologue: phase 1 = exact fp32 network at DD Chebyshev nodes (+Wo fold),
// phase 2 (after 12-block grid barrier) = DCT-II -> coefficients.
// 12 blocks x 512 threads; thread (q,c): q = k-quarter / node slot, c = column.
// Weight prefetch double-buffers the next layer's 32 LDGs under current compute.
// ---------------------------------------------------------------------------
__global__ __launch_bounds__(NE_THREADS) void prologue_kernel(
    const float* __restrict__ x,
    const float* __restrict__ W10, const float* __restrict__ b10,
    const float* __restrict__ W20, const float* __restrict__ b20,
    const float* __restrict__ W11, const float* __restrict__ b11,
    const float* __restrict__ W21, const float* __restrict__ b21,
    const float* __restrict__ W12, const float* __restrict__ b12,
    const float* __restrict__ W22, const float* __restrict__ b22,
    const float* __restrict__ Wo)
{
    __shared__ float red[NE_THREADS];
    __shared__ float buf[NODES][HID];          // current activations
    __shared__ float part[KSPL][NODES][HID];   // per-quarter partials
    __shared__ float costab[NODES][DD];        // phase 2: cos table (4 k x 48 m)
    __shared__ float sG[DD][HID];              // phase 2: staged G (24KB)

    const int c = threadIdx.x & (HID - 1);
    const int q = threadIdx.x >> 7;            // 0..3
    const int k0 = q * (HID / KSPL);           // 32 k's per quarter

    const float* Ws[6] = {W20, W11, W21, W12, W22, Wo};
    const float* bs[6] = {b20, b11, b21, b12, b22, (const float*)0};

    // issue layer-0 weight loads early (independent of everything below)
    float wc[HID / KSPL];
    #pragma unroll
    for (int kk = 0; kk < HID / KSPL; kk++) wc[kk] = Ws[0][(k0 + kk) * HID + c];

    // dmax = 2*max||x|| (triangle-inequality bound), deterministic per block
    float mx = 0.0f;
    for (int t = threadIdx.x; t < BB * NN; t += NE_THREADS) {
        float a = x[2 * t], b = x[2 * t + 1];
        mx = fmaxf(mx, fmaf(a, a, b * b));
    }
    red[threadIdx.x] = mx;
    __syncthreads();
    #pragma unroll
    for (int s = NE_THREADS / 2; s > 0; s >>= 1) {
        if (threadIdx.x < s) red[threadIdx.x] = fmaxf(red[threadIdx.x], red[threadIdx.x + s]);
        __syncthreads();
    }
    const float dmax = 2.0f * sqrtf(red[0]) * 1.000001f + 1e-6f;
    if (blockIdx.x == 0 && threadIdx.x == 0) g_inv_hd = 2.0f / dmax;

    // layer 0 (scalar input): thread-set q computes node q of this block
    {
        int mnode = blockIdx.x * NODES + q;
        float d = 0.5f * (cospif((mnode + 0.5f) * (1.0f / DD)) + 1.0f) * dmax;
        float a = fmaf(d, W10[c], b10[c]);
        buf[q][c] = a / (1.0f + expf(-a));
    }
    __syncthreads();

    #pragma unroll
    for (int l = 0; l < 6; l++) {
        // prefetch next layer's weights (hides LDG latency under compute+syncs)
        float wn[HID / KSPL];
        if (l < 5) {
            #pragma unroll
            for (int kk = 0; kk < HID / KSPL; kk++)
                wn[kk] = Ws[l + 1][(k0 + kk) * HID + c];
        }
        float h0 = 0.0f, h1 = 0.0f, h2 = 0.0f, h3 = 0.0f;
        #pragma unroll
        for (int kk = 0; kk < HID / KSPL; kk++) {
            const int k = k0 + kk;
            const float w = wc[kk];
            h0 = fmaf(buf[0][k], w, h0);
            h1 = fmaf(buf[1][k], w, h1);
            h2 = fmaf(buf[2][k], w, h2);
            h3 = fmaf(buf[3][k], w, h3);
        }
        part[q][0][c] = h0;
        part[q][1][c] = h1;
        part[q][2][c] = h2;
        part[q][3][c] = h3;
        __syncthreads();
        float v = (bs[l] ? bs[l][c] : 0.0f) +
                  ((part[0][q][c] + part[1][q][c]) + (part[2][q][c] + part[3][q][c]));
        if (l == 1 || l == 3) v = v / (1.0f + expf(-v));   // silu after W1_1, W1_2
        if (l < 5) buf[q][c] = v;                          // reads of buf done pre-sync
        else g_G[(blockIdx.x * NODES + q) * HID + c] = v;
        __syncthreads();
        #pragma unroll
        for (int kk = 0; kk < HID / KSPL; kk++) wc[kk] = wn[kk];
    }

    // ---- grid barrier across the 12 co-resident blocks (replay-safe) ----
    __threadfence();
    if (threadIdx.x == 0) {
        atomicAdd(&g_arrive, 1u);
        while (*(volatile unsigned*)&g_arrive < (unsigned)NE_BLOCKS) __nanosleep(32);
    }
    __syncthreads();
    __threadfence();

    // ---- phase 2: DCT-II. Block handles k = blockIdx*4 + q. ----
    // cos table: 4*48 = 192 distinct angles per block (vs 24.5K redundant MUFUs)
    for (int t = threadIdx.x; t < NODES * DD; t += NE_THREADS) {
        int qq = t / DD, m = t - qq * DD;
        int k = blockIdx.x * NODES + qq;
        int num = (k * (2 * m + 1)) % (4 * DD);   // cospi period 2 -> mod 192
        costab[qq][m] = cospif((float)num * (1.0f / (2.0f * DD)));
    }
    // stage G in smem (vectorized, L1-bypassing: cross-block data)
    for (int t = threadIdx.x; t < DD * HID / 4; t += NE_THREADS)
        reinterpret_cast<float4*>(sG)[t] =
            __ldcg(reinterpret_cast<const float4*>(g_G) + t);
    __syncthreads();

    {
        int k = blockIdx.x * NODES + q;
        float acc = 0.0f;
        #pragma unroll
        for (int m = 0; m < DD; m++) acc = fmaf(costab[q][m], sG[m][c], acc);
        float wgt = (k == 0) ? (1.0f / DD) : (2.0f / DD);
        g_C[k * HID + c] = acc * wgt;
    }

    // exit: restore barrier counter to 0 for the next graph replay
    __syncthreads();
    if (threadIdx.x == 0) atomicSub(&g_arrive, 1u);
}

// ---------------------------------------------------------------------------
// Hot kernel: per (b,i), s[k] = sum_j T_k(z_ij); out = (1/N) s@C + bo.
// 512 blocks x 128 thr: block = 2 rows x 2 warps/row (j-split 256 each).
// 4 independent recurrence chains per lane hide FMA lat-4.
// Butterfly runs on SPAD=64 padded array (s[48..63] == 0) for clean mapping.
// ---------------------------------------------------------------------------
__global__ __launch_bounds__(128, 5) void cheb_main_kernel(
    const float* __restrict__ x, const float* __restrict__ bo,
    float* __restrict__ out)
{
    __shared__ float sx[NN * 2];
    __shared__ float sred[4][SPAD];        // per-warp reduced s

    const float inv_hd = g_inv_hd;         // published by prologue

    const int b = blockIdx.x >> 8;         // 256 blocks per batch
    for (int t = threadIdx.x; t < NN * 2; t += 128) sx[t] = x[b * NN * 2 + t];
    __syncthreads();

    const int w    = threadIdx.x >> 5;     // warp 0..3
    const int lane = threadIdx.x & 31;
    const int r    = w >> 1;               // row-in-block 0..1
    const int h    = w & 1;                // j-half 0..1
    const int i    = ((blockIdx.x & 255) << 1) + r;   // row within batch
    const float xi0 = sx[2 * i], xi1 = sx[2 * i + 1];

    float s[SPAD];
    #pragma unroll
    for (int k = 0; k < SPAD; k++) s[k] = 0.0f;

    #pragma unroll 1
    for (int jj = 0; jj < 2; jj++) {
        const int j0 = h * 256 + jj * 128;
        const int ja = j0 + lane, jb = ja + 32, jc = ja + 64, jd = ja + 96;
        float dxa = xi0 - sx[2 * ja], dya = xi1 - sx[2 * ja + 1];
        float dxb = xi0 - sx[2 * jb], dyb = xi1 - sx[2 * jb + 1];
        float dxc = xi0 - sx[2 * jc], dyc = xi1 - sx[2 * jc + 1];
        float dxd = xi0 - sx[2 * jd], dyd = xi1 - sx[2 * jd + 1];
        float za = fmaf(sqrtf(fmaf(dxa, dxa, dya * dya)), inv_hd, -1.0f);
        float zb = fmaf(sqrtf(fmaf(dxb, dxb, dyb * dyb)), inv_hd, -1.0f);
        float zc = fmaf(sqrtf(fmaf(dxc, dxc, dyc * dyc)), inv_hd, -1.0f);
        float zd = fmaf(sqrtf(fmaf(dxd, dxd, dyd * dyd)), inv_hd, -1.0f);
        za = fminf(fmaxf(za, -1.0f), 1.0f);
        zb = fminf(fmaxf(zb, -1.0f), 1.0f);
        zc = fminf(fmaxf(zc, -1.0f), 1.0f);
        zd = fminf(fmaxf(zd, -1.0f), 1.0f);

        s[1] += (za + zb) + (zc + zd);
        float t0a = 1.0f, t1a = za, z2a = za + za;
        float t0b = 1.0f, t1b = zb, z2b = zb + zb;
        float t0c = 1.0f, t1c = zc, z2c = zc + zc;
        float t0d = 1.0f, t1d = zd, z2d = zd + zd;
        #pragma unroll
        for (int k = 2; k < DD; k++) {
            float ta = fmaf(z2a, t1a, -t0a); t0a = t1a; t1a = ta;
            float tb = fmaf(z2b, t1b, -t0b); t0b = t1b; t1b = tb;
            float tc = fmaf(z2c, t1c, -t0c); t0c = t1c; t1c = tc;
            float td = fmaf(z2d, t1d, -t0d); t0d = t1d; t1d = td;
            s[k] += (ta + tb) + (tc + td);
        }
    }
    // T_0 == 1: each lane processed 256/32 = 8 source nodes
    s[0] = 8.0f;

    // reduce-scatter butterfly over SPAD: lane ends with k = 2*lane + {0,1}
    int len = SPAD / 2;
    #pragma unroll
    for (int off = 16; off > 0; off >>= 1) {
        const bool hi = (lane & off) != 0;
        #pragma unroll
        for (int k = 0; k < 32; k++) {     // bounded by first-stage len
            if (k >= len) break;
            float send = hi ? s[k] : s[k + len];
            float recv = __shfl_xor_sync(0xffffffffu, send, off);
            s[k] = (hi ? s[k + len] : s[k]) + recv;
        }
        len >>= 1;
    }
    sred[w][2 * lane]     = s[0];
    sred[w][2 * lane + 1] = s[1];
    __syncthreads();

    // combine the row's two j-halves, contract with C (warp owns 64 columns)
    const float sc = 1.0f / (float)NN;
    const int c0 = h * 64 + lane * 2;
    float accx = bo[c0], accy = bo[c0 + 1];
    #pragma unroll 8
    for (int k = 0; k < DD; k++) {
        float sk = (sred[2 * r][k] + sred[2 * r + 1][k]) * sc;
        float2 wv = *reinterpret_cast<const float2*>(&g_C[k * HID + c0]);
        accx = fmaf(sk, wv.x, accx);
        accy = fmaf(sk, wv.y, accy);
    }
    const int gi = b * NN + i;
    *reinterpret_cast<float2*>(&out[gi * HID + c0]) = make_float2(accx, accy);
}

// ---------------------------------------------------------------------------
// Launch: 2 graph-capturable kernels.
// Input order: x, W1_0,b1_0,W2_0,b2_0, W1_1,b1_1,W2_1,b2_1, W1_2,b1_2,W2_2,b2_2, Wo,bo
// ---------------------------------------------------------------------------
extern "C" void kernel_launch(void* const* d_in, const int* in_sizes, int n_in,
                              void* d_out, int out_size)
{
    const float* x   = (const float*)d_in[0];
    const float* W10 = (const float*)d_in[1];
    const float* b10 = (const float*)d_in[2];
    const float* W20 = (const float*)d_in[3];
    const float* b20 = (const float*)d_in[4];
    const float* W11 = (const float*)d_in[5];
    const float* b11 = (const float*)d_in[6];
    const float* W21 = (const float*)d_in[7];
    const float* b21 = (const float*)d_in[8];
    const float* W12 = (const float*)d_in[9];
    const float* b12 = (const float*)d_in[10];
    const float* W22 = (const float*)d_in[11];
    const float* b22 = (const float*)d_in[12];
    const float* Wo  = (const float*)d_in[13];
    const float* bo  = (const float*)d_in[14];
    float* out = (float*)d_out;

    prologue_kernel<<<NE_BLOCKS, NE_THREADS>>>(x, W10, b10, W20, b20, W11, b11,
                                               W21, b21, W12, b12, W22, b22, Wo);
    cheb_main_kernel<<<(BB * NN) / 2, 128>>>(x, bo, out);
}